// round 1
// baseline (speedup 1.0000x reference)
#include <cuda_runtime.h>
#include <math.h>

#define N_ITEMS 7000
#define N_USERS 30000
#define N_NODES 37000
#define DIM     128
#define E_EDGES 400000
#define R_REL   10
#define NBASES  8
#define B_BATCH 512
#define L_CTX   100

// ---------------- device scratch (static; no allocation) ----------------
__device__ float g_wmsg[(size_t)R_REL * N_ITEMS * DIM];   // 35.84 MB
__device__ float g_user[(size_t)N_USERS * DIM];           // 15.36 MB
__device__ float g_item[(size_t)N_ITEMS * DIM];           //  3.58 MB
__device__ float g_score[N_ITEMS];
__device__ int   g_has[N_ITEMS];

__device__ int g_cnt_src[N_ITEMS];
__device__ int g_off_src[N_ITEMS + 1];
__device__ int g_cur_src[N_ITEMS];
__device__ int g_csr_src[E_EDGES];        // user-local id per edge, sorted by src item

__device__ int g_cnt_dst[N_USERS];
__device__ int g_off_dst[N_USERS + 1];
__device__ int g_cur_dst[N_USERS];
__device__ int g_csr_dst[E_EDGES];        // packed src*16+type, sorted by dst user

__device__ float g_pool[2 * B_BATCH * DIM];
__device__ float g_hid[B_BATCH * DIM];
__device__ int   g_is64;

// ---------------- index dtype sniffing (int32 vs int64 inputs) ----------------
__global__ void k_detect(const int* ei32) {
    if (threadIdx.x == 0) {
        int s = 0;
        for (int k = 1; k < 64; k += 2) s |= ei32[k];  // int64 -> high words all 0
        g_is64 = (s == 0) ? 1 : 0;
    }
}
__device__ __forceinline__ int geti(const void* p, long long i, int is64) {
    if (is64) return (int)((const long long*)p)[i];
    return ((const int*)p)[i];
}

// ---------------- zero per-call state ----------------
__global__ void k_zero() {
    int i = blockIdx.x * blockDim.x + threadIdx.x;
    if (i < N_ITEMS) { g_cnt_src[i] = 0; g_cur_src[i] = 0; }
    if (i < N_USERS) { g_cnt_dst[i] = 0; g_cur_dst[i] = 0; }
}

// ---------------- per-(relation,item) message table ----------------
__global__ void k_wmsg(const float* __restrict__ basis, const float* __restrict__ comp) {
    __shared__ float sc[R_REL * NBASES];
    int i = blockIdx.x;
    int d = threadIdx.x;
    if (d < R_REL * NBASES) sc[d] = comp[d];
    __syncthreads();
    float bv[NBASES];
#pragma unroll
    for (int b = 0; b < NBASES; b++)
        bv[b] = basis[(size_t)b * N_NODES * DIM + (size_t)i * DIM + d];
#pragma unroll
    for (int r = 0; r < R_REL; r++) {
        float acc = 0.f;
#pragma unroll
        for (int b = 0; b < NBASES; b++) acc += sc[r * NBASES + b] * bv[b];
        g_wmsg[((size_t)r * N_ITEMS + i) * DIM + d] = acc;
    }
}

// ---------------- histogram ----------------
__global__ void k_hist(const void* __restrict__ ei) {
    int e = blockIdx.x * blockDim.x + threadIdx.x;
    if (e >= E_EDGES) return;
    int is64 = g_is64;
    int s = geti(ei, e, is64);
    int u = geti(ei, (long long)E_EDGES + e, is64) - N_ITEMS;
    atomicAdd(&g_cnt_src[s], 1);
    atomicAdd(&g_cnt_dst[u], 1);
}

// ---------------- single-block exclusive scan ----------------
__device__ void scan_body(const int* __restrict__ cnt, int* __restrict__ off, int n) {
    __shared__ int tmp[1024];
    __shared__ int carry;
    if (threadIdx.x == 0) carry = 0;
    __syncthreads();
    for (int base = 0; base < n; base += 1024) {
        int i = base + (int)threadIdx.x;
        int v = (i < n) ? cnt[i] : 0;
        tmp[threadIdx.x] = v;
        __syncthreads();
        for (int o = 1; o < 1024; o <<= 1) {
            int add = (threadIdx.x >= (unsigned)o) ? tmp[threadIdx.x - o] : 0;
            __syncthreads();
            tmp[threadIdx.x] += add;
            __syncthreads();
        }
        if (i < n) off[i] = carry + tmp[threadIdx.x] - v;
        __syncthreads();
        if (threadIdx.x == 1023) carry += tmp[1023];
        __syncthreads();
    }
    if (threadIdx.x == 0) off[n] = carry;
}
__global__ void k_scan_src() { scan_body(g_cnt_src, g_off_src, N_ITEMS); }
__global__ void k_scan_dst() { scan_body(g_cnt_dst, g_off_dst, N_USERS); }

// ---------------- CSR scatter (counting sort) ----------------
__global__ void k_scatter(const void* __restrict__ ei, const void* __restrict__ et) {
    int e = blockIdx.x * blockDim.x + threadIdx.x;
    if (e >= E_EDGES) return;
    int is64 = g_is64;
    int s = geti(ei, e, is64);
    int u = geti(ei, (long long)E_EDGES + e, is64) - N_ITEMS;
    int t = geti(et, e, is64);
    int p = g_off_src[s] + atomicAdd(&g_cur_src[s], 1);
    g_csr_src[p] = u;
    int q = g_off_dst[u] + atomicAdd(&g_cur_dst[u], 1);
    g_csr_dst[q] = s * 16 + t;
}

// ---------------- per-user embedding: root + bias + sum_r mean_r ----------------
__global__ void k_user(const float* __restrict__ root, const float* __restrict__ bias) {
    __shared__ int   scnt[8][R_REL];
    __shared__ float sinv[8][R_REL];
    int w = threadIdx.x >> 5, lane = threadIdx.x & 31;
    int u = blockIdx.x * 8 + w;
    if (u >= N_USERS) return;
    int beg = g_off_dst[u], end = g_off_dst[u + 1];
    if (lane < R_REL) scnt[w][lane] = 0;
    __syncwarp();
    for (int e = beg + lane; e < end; e += 32)
        atomicAdd(&scnt[w][g_csr_dst[e] & 15], 1);
    __syncwarp();
    if (lane < R_REL)
        sinv[w][lane] = scnt[w][lane] > 0 ? 1.f / (float)scnt[w][lane] : 0.f;
    __syncwarp();
    float4 acc = make_float4(0.f, 0.f, 0.f, 0.f);
    for (int e = beg; e < end; e++) {
        int pk = g_csr_dst[e];                 // broadcast load
        int s = pk >> 4, t = pk & 15;
        float iv = sinv[w][t];
        float4 v = ((const float4*)&g_wmsg[((size_t)t * N_ITEMS + s) * DIM])[lane];
        acc.x += iv * v.x; acc.y += iv * v.y; acc.z += iv * v.z; acc.w += iv * v.w;
    }
    int g = N_ITEMS + u;
    float4 rv = ((const float4*)&root[(size_t)g * DIM])[lane];
    float4 bv = ((const float4*)bias)[lane];
    ((float4*)&g_user[(size_t)u * DIM])[lane] =
        make_float4(acc.x + rv.x + bv.x, acc.y + rv.y + bv.y,
                    acc.z + rv.z + bv.z, acc.w + rv.w + bv.w);
}

// ---------------- per-item mean of connected users ----------------
__global__ void k_item() {
    int w = threadIdx.x >> 5, lane = threadIdx.x & 31;
    int i = blockIdx.x * 8 + w;
    if (i >= N_ITEMS) return;
    int beg = g_off_src[i], end = g_off_src[i + 1];
    float4 acc = make_float4(0.f, 0.f, 0.f, 0.f);
    for (int e = beg; e < end; e++) {
        int u = g_csr_src[e];                  // broadcast load
        float4 v = ((const float4*)&g_user[(size_t)u * DIM])[lane];
        acc.x += v.x; acc.y += v.y; acc.z += v.z; acc.w += v.w;
    }
    int deg = end - beg;
    float iv = deg > 0 ? 1.f / (float)deg : 0.f;
    ((float4*)&g_item[(size_t)i * DIM])[lane] =
        make_float4(acc.x * iv, acc.y * iv, acc.z * iv, acc.w * iv);
    if (lane == 0) g_has[i] = (deg > 0) ? 1 : 0;
}

// ---------------- per-item attention score: tanh(h@A)·b ----------------
__global__ void k_score(const float* __restrict__ attn_a, const float* __restrict__ attn_b) {
    __shared__ float h[DIM];
    __shared__ float red[DIM];
    int i = blockIdx.x, tid = threadIdx.x;
    h[tid] = g_item[(size_t)i * DIM + tid];
    __syncthreads();
    float acc = 0.f;
#pragma unroll 8
    for (int k = 0; k < DIM; k++) acc += h[k] * attn_a[k * DIM + tid];
    red[tid] = tanhf(acc) * attn_b[tid];
    __syncthreads();
    for (int o = 64; o > 0; o >>= 1) {
        if (tid < o) red[tid] += red[tid + o];
        __syncthreads();
    }
    if (tid == 0) g_score[i] = red[0];
}

// ---------------- masked softmax pooling over context items ----------------
__global__ void k_pool(const void* __restrict__ ctx, float* __restrict__ out) {
    __shared__ float sw[L_CTX];
    __shared__ int   sidx[L_CTX];
    __shared__ float smax, sinv;
    int b = blockIdx.x, tid = threadIdx.x;
    if (tid < L_CTX) {
        int idx = geti(ctx, (long long)b * L_CTX + tid, g_is64);
        int valid = (idx >= 0) && g_has[idx];
        sidx[tid] = valid ? idx : -1;
        sw[tid] = valid ? g_score[idx] : -1e30f;
    }
    __syncthreads();
    if (tid == 0) {
        float m = -1e30f;
        for (int l = 0; l < L_CTX; l++) m = fmaxf(m, sw[l]);
        smax = m;
    }
    __syncthreads();
    if (tid < L_CTX) sw[tid] = (sidx[tid] >= 0) ? expf(sw[tid] - smax) : 0.f;
    __syncthreads();
    if (tid == 0) {
        float s = 0.f;
        for (int l = 0; l < L_CTX; l++) s += sw[l];
        sinv = (s > 0.f) ? 1.f / s : 0.f;
    }
    __syncthreads();
    float acc = 0.f;
    for (int l = 0; l < L_CTX; l++) {
        float wgt = sw[l];
        if (wgt > 0.f) acc += wgt * g_item[(size_t)sidx[l] * DIM + tid];
    }
    out[(size_t)b * DIM + tid] = acc * sinv;
}

// ---------------- tiny MLP layers: Y = relu(X @ W + b) ----------------
__global__ void k_mlp(const float* __restrict__ X, const float* __restrict__ W,
                      const float* __restrict__ bv, float* __restrict__ Y) {
    __shared__ float xs[DIM];
    int b = blockIdx.x, j = threadIdx.x;
    xs[j] = X[(size_t)b * DIM + j];
    __syncthreads();
    float acc = bv[j];
#pragma unroll 8
    for (int k = 0; k < DIM; k++) acc += xs[k] * W[k * DIM + j];
    Y[(size_t)b * DIM + j] = fmaxf(acc, 0.f);
}
__global__ void k_mlp2(const float* __restrict__ X1, const float* __restrict__ X2,
                       const float* __restrict__ W, const float* __restrict__ bv,
                       float* __restrict__ Y) {
    __shared__ float xs[2 * DIM];
    int b = blockIdx.x, j = threadIdx.x;
    xs[j] = X1[(size_t)b * DIM + j];
    xs[DIM + j] = X2[(size_t)b * DIM + j];
    __syncthreads();
    float acc = bv[j];
#pragma unroll 8
    for (int k = 0; k < 2 * DIM; k++) acc += xs[k] * W[k * DIM + j];
    Y[(size_t)b * DIM + j] = fmaxf(acc, 0.f);
}

// ---------------- launch ----------------
extern "C" void kernel_launch(void* const* d_in, const int* in_sizes, int n_in,
                              void* d_out, int out_size) {
    const void*  ei     = d_in[0];
    const void*  et     = d_in[1];
    const void*  ctx_i  = d_in[2];
    const void*  ctx_r  = d_in[3];
    const float* basis  = (const float*)d_in[4];
    const float* comp   = (const float*)d_in[5];
    const float* root   = (const float*)d_in[6];
    const float* bias   = (const float*)d_in[7];
    const float* attn_a = (const float*)d_in[8];
    const float* attn_b = (const float*)d_in[9];
    const float* fc1_w  = (const float*)d_in[10];
    const float* fc1_b  = (const float*)d_in[11];
    const float* fc2_w  = (const float*)d_in[12];
    const float* fc2_b  = (const float*)d_in[13];
    const float* efc1_w = (const float*)d_in[14];
    const float* efc1_b = (const float*)d_in[15];
    const float* efc2_w = (const float*)d_in[16];
    const float* efc2_b = (const float*)d_in[17];
    float* out = (float*)d_out;

    float* pool = nullptr;
    float* hid = nullptr;
    cudaGetSymbolAddress((void**)&pool, g_pool);
    cudaGetSymbolAddress((void**)&hid, g_hid);
    float* pool0 = pool;
    float* pool1 = pool + B_BATCH * DIM;
    float* p_init = out + B_BATCH * DIM;       // output layout: [profile | p_init | p_resp]
    float* p_resp = out + 2 * B_BATCH * DIM;

    k_detect<<<1, 32>>>((const int*)ei);
    k_zero<<<(N_USERS + 255) / 256, 256>>>();
    k_wmsg<<<N_ITEMS, DIM>>>(basis, comp);
    k_hist<<<(E_EDGES + 255) / 256, 256>>>(ei);
    k_scan_src<<<1, 1024>>>();
    k_scan_dst<<<1, 1024>>>();
    k_scatter<<<(E_EDGES + 255) / 256, 256>>>(ei, et);
    k_user<<<(N_USERS + 7) / 8, 256>>>(root, bias);
    k_item<<<(N_ITEMS + 7) / 8, 256>>>();
    k_score<<<N_ITEMS, DIM>>>(attn_a, attn_b);
    k_pool<<<B_BATCH, DIM>>>(ctx_i, pool0);
    k_pool<<<B_BATCH, DIM>>>(ctx_r, pool1);

    k_mlp<<<B_BATCH, DIM>>>(pool0, fc1_w, fc1_b, hid);
    k_mlp<<<B_BATCH, DIM>>>(hid, fc2_w, fc2_b, p_init);
    k_mlp<<<B_BATCH, DIM>>>(pool1, fc1_w, fc1_b, hid);
    k_mlp<<<B_BATCH, DIM>>>(hid, fc2_w, fc2_b, p_resp);
    k_mlp2<<<B_BATCH, DIM>>>(p_init, p_resp, efc1_w, efc1_b, hid);
    k_mlp<<<B_BATCH, DIM>>>(hid, efc2_w, efc2_b, out);
}

// round 2
// speedup vs baseline: 1.0793x; 1.0793x over previous
#include <cuda_runtime.h>
#include <math.h>

#define N_ITEMS 7000
#define N_USERS 30000
#define N_NODES 37000
#define DIM     128
#define E_EDGES 400000
#define R_REL   10
#define NBASES  8
#define B_BATCH 512
#define L_CTX   100

// ---------------- device scratch (static; no allocation) ----------------
__device__ float g_wmsg[(size_t)R_REL * N_ITEMS * DIM];   // 35.84 MB
__device__ float g_user[(size_t)N_USERS * DIM];           // 15.36 MB
__device__ float g_item[(size_t)N_ITEMS * DIM];           //  3.58 MB
__device__ float g_score[N_ITEMS];
__device__ int   g_has[N_ITEMS];

__device__ int g_cnt_src[N_ITEMS];
__device__ int g_off_src[N_ITEMS + 1];
__device__ int g_csr_src[E_EDGES];        // user-local id per edge, grouped by src item

__device__ int g_cnt_dst[N_USERS];
__device__ int g_off_dst[N_USERS + 1];
__device__ int g_csr_dst[E_EDGES];        // packed src*16+type, grouped by dst user

__device__ unsigned int g_pack[E_EDGES];  // (s<<19)|(t<<15)|u

__device__ float g_pool[2 * B_BATCH * DIM];
__device__ int   g_is64;

// ---------------- index dtype sniffing (int32 vs int64 inputs) ----------------
__global__ void k_detect(const int* ei32) {
    if (threadIdx.x == 0) {
        int s = 0;
        for (int k = 1; k < 64; k += 2) s |= ei32[k];  // int64 -> high words all 0
        g_is64 = (s == 0) ? 1 : 0;
    }
}
__device__ __forceinline__ int geti(const void* p, long long i, int is64) {
    if (is64) return (int)((const long long*)p)[i];
    return ((const int*)p)[i];
}

// ---------------- zero per-call state ----------------
__global__ void k_zero() {
    int i = blockIdx.x * blockDim.x + threadIdx.x;
    if (i < N_ITEMS) g_cnt_src[i] = 0;
    if (i < N_USERS) g_cnt_dst[i] = 0;
}

// ---------------- per-(relation,item) message table ----------------
__global__ void k_wmsg(const float* __restrict__ basis, const float* __restrict__ comp) {
    __shared__ float sc[R_REL * NBASES];
    int i = blockIdx.x;
    int d = threadIdx.x;
    if (d < R_REL * NBASES) sc[d] = comp[d];
    __syncthreads();
    float bv[NBASES];
#pragma unroll
    for (int b = 0; b < NBASES; b++)
        bv[b] = basis[(size_t)b * N_NODES * DIM + (size_t)i * DIM + d];
#pragma unroll
    for (int r = 0; r < R_REL; r++) {
        float acc = 0.f;
#pragma unroll
        for (int b = 0; b < NBASES; b++) acc += sc[r * NBASES + b] * bv[b];
        g_wmsg[((size_t)r * N_ITEMS + i) * DIM + d] = acc;
    }
}

// ---------------- histogram + edge packing ----------------
__global__ void k_hist(const void* __restrict__ ei, const void* __restrict__ et) {
    int e = blockIdx.x * blockDim.x + threadIdx.x;
    if (e >= E_EDGES) return;
    int is64 = g_is64;
    int s = geti(ei, e, is64);
    int u = geti(ei, (long long)E_EDGES + e, is64) - N_ITEMS;
    int t = geti(et, e, is64);
    g_pack[e] = ((unsigned)s << 19) | ((unsigned)t << 15) | (unsigned)u;
    atomicAdd(&g_cnt_src[s], 1);
    atomicAdd(&g_cnt_dst[u], 1);
}

// ---------------- warp-shuffle exclusive scan (both arrays, 2 blocks) ----------------
__device__ void scan_dev(const int* __restrict__ cnt, int* __restrict__ off, int n) {
    __shared__ int wsum[32];
    int lane = threadIdx.x & 31, w = threadIdx.x >> 5;
    int carry = 0;
    for (int base = 0; base < n; base += 1024) {
        int i = base + (int)threadIdx.x;
        int v = (i < n) ? cnt[i] : 0;
        int x = v;
#pragma unroll
        for (int o = 1; o < 32; o <<= 1) {
            int y = __shfl_up_sync(0xffffffffu, x, o);
            if (lane >= o) x += y;
        }
        if (lane == 31) wsum[w] = x;
        __syncthreads();
        if (w == 0) {
            int s = wsum[lane];
#pragma unroll
            for (int o = 1; o < 32; o <<= 1) {
                int y = __shfl_up_sync(0xffffffffu, s, o);
                if (lane >= o) s += y;
            }
            wsum[lane] = s;
        }
        __syncthreads();
        int woff = (w > 0) ? wsum[w - 1] : 0;
        if (i < n) off[i] = carry + woff + x - v;
        carry += wsum[31];
        __syncthreads();
    }
    if (threadIdx.x == 0) off[n] = carry;
}
__global__ void k_scan() {
    if (blockIdx.x == 0) scan_dev(g_cnt_src, g_off_src, N_ITEMS);
    else                 scan_dev(g_cnt_dst, g_off_dst, N_USERS);
}

// ---------------- CSR scatter (reuses cnt as countdown cursors) ----------------
__global__ void k_scatter() {
    int e = blockIdx.x * blockDim.x + threadIdx.x;
    if (e >= E_EDGES) return;
    unsigned pk = g_pack[e];
    int s = (int)(pk >> 19);
    int t = (int)((pk >> 15) & 15u);
    int u = (int)(pk & 0x7fffu);
    int p = g_off_src[s] + (atomicAdd(&g_cnt_src[s], -1) - 1);
    g_csr_src[p] = u;
    int q = g_off_dst[u] + (atomicAdd(&g_cnt_dst[u], -1) - 1);
    g_csr_dst[q] = s * 16 + t;
}

// ---------------- per-user embedding: root + bias + sum_r mean_r ----------------
__global__ void k_user(const float* __restrict__ root, const float* __restrict__ bias) {
    __shared__ int   scnt[8][16];
    __shared__ float sinv[8][16];
    int w = threadIdx.x >> 5, lane = threadIdx.x & 31;
    int u = blockIdx.x * 8 + w;
    if (u >= N_USERS) return;
    int beg = g_off_dst[u], end = g_off_dst[u + 1];
    if (lane < 16) scnt[w][lane] = 0;
    __syncwarp();
    for (int e = beg + lane; e < end; e += 32)
        atomicAdd(&scnt[w][g_csr_dst[e] & 15], 1);
    __syncwarp();
    if (lane < 16)
        sinv[w][lane] = scnt[w][lane] > 0 ? 1.f / (float)scnt[w][lane] : 0.f;
    __syncwarp();
    float4 acc = make_float4(0.f, 0.f, 0.f, 0.f);
    int e = beg;
    for (; e + 4 <= end; e += 4) {
        int p0 = g_csr_dst[e], p1 = g_csr_dst[e + 1];
        int p2 = g_csr_dst[e + 2], p3 = g_csr_dst[e + 3];
        float4 v0 = ((const float4*)&g_wmsg[((size_t)(p0 & 15) * N_ITEMS + (p0 >> 4)) * DIM])[lane];
        float4 v1 = ((const float4*)&g_wmsg[((size_t)(p1 & 15) * N_ITEMS + (p1 >> 4)) * DIM])[lane];
        float4 v2 = ((const float4*)&g_wmsg[((size_t)(p2 & 15) * N_ITEMS + (p2 >> 4)) * DIM])[lane];
        float4 v3 = ((const float4*)&g_wmsg[((size_t)(p3 & 15) * N_ITEMS + (p3 >> 4)) * DIM])[lane];
        float i0 = sinv[w][p0 & 15], i1 = sinv[w][p1 & 15];
        float i2 = sinv[w][p2 & 15], i3 = sinv[w][p3 & 15];
        acc.x += i0 * v0.x + i1 * v1.x + i2 * v2.x + i3 * v3.x;
        acc.y += i0 * v0.y + i1 * v1.y + i2 * v2.y + i3 * v3.y;
        acc.z += i0 * v0.z + i1 * v1.z + i2 * v2.z + i3 * v3.z;
        acc.w += i0 * v0.w + i1 * v1.w + i2 * v2.w + i3 * v3.w;
    }
    for (; e < end; e++) {
        int pk = g_csr_dst[e];
        float iv = sinv[w][pk & 15];
        float4 v = ((const float4*)&g_wmsg[((size_t)(pk & 15) * N_ITEMS + (pk >> 4)) * DIM])[lane];
        acc.x += iv * v.x; acc.y += iv * v.y; acc.z += iv * v.z; acc.w += iv * v.w;
    }
    int g = N_ITEMS + u;
    float4 rv = ((const float4*)&root[(size_t)g * DIM])[lane];
    float4 bv = ((const float4*)bias)[lane];
    ((float4*)&g_user[(size_t)u * DIM])[lane] =
        make_float4(acc.x + rv.x + bv.x, acc.y + rv.y + bv.y,
                    acc.z + rv.z + bv.z, acc.w + rv.w + bv.w);
}

// ---------------- per-item mean of connected users ----------------
__global__ void k_item() {
    int w = threadIdx.x >> 5, lane = threadIdx.x & 31;
    int i = blockIdx.x * 8 + w;
    if (i >= N_ITEMS) return;
    int beg = g_off_src[i], end = g_off_src[i + 1];
    float4 acc = make_float4(0.f, 0.f, 0.f, 0.f);
    int e = beg;
    for (; e + 4 <= end; e += 4) {
        int u0 = g_csr_src[e], u1 = g_csr_src[e + 1];
        int u2 = g_csr_src[e + 2], u3 = g_csr_src[e + 3];
        float4 v0 = ((const float4*)&g_user[(size_t)u0 * DIM])[lane];
        float4 v1 = ((const float4*)&g_user[(size_t)u1 * DIM])[lane];
        float4 v2 = ((const float4*)&g_user[(size_t)u2 * DIM])[lane];
        float4 v3 = ((const float4*)&g_user[(size_t)u3 * DIM])[lane];
        acc.x += v0.x + v1.x + v2.x + v3.x;
        acc.y += v0.y + v1.y + v2.y + v3.y;
        acc.z += v0.z + v1.z + v2.z + v3.z;
        acc.w += v0.w + v1.w + v2.w + v3.w;
    }
    for (; e < end; e++) {
        float4 v = ((const float4*)&g_user[(size_t)g_csr_src[e] * DIM])[lane];
        acc.x += v.x; acc.y += v.y; acc.z += v.z; acc.w += v.w;
    }
    int deg = end - beg;
    float iv = deg > 0 ? 1.f / (float)deg : 0.f;
    ((float4*)&g_item[(size_t)i * DIM])[lane] =
        make_float4(acc.x * iv, acc.y * iv, acc.z * iv, acc.w * iv);
    if (lane == 0) g_has[i] = (deg > 0) ? 1 : 0;
}

// ---------------- batched per-item attention score: tanh(h@A)·b ----------------
#define IPB 32
__global__ void k_score(const float* __restrict__ attn_a, const float* __restrict__ attn_b) {
    __shared__ float h[IPB][DIM];
    __shared__ float sc[IPB][DIM + 1];
    int i0 = blockIdx.x * IPB;
    int tid = threadIdx.x;      // 128
    for (int idx = tid; idx < IPB * DIM / 4; idx += 128) {
        int ii = idx / (DIM / 4), kk = idx % (DIM / 4);
        float4 v = (i0 + ii < N_ITEMS)
                   ? ((const float4*)&g_item[(size_t)(i0 + ii) * DIM])[kk]
                   : make_float4(0.f, 0.f, 0.f, 0.f);
        ((float4*)h[ii])[kk] = v;
    }
    __syncthreads();
    int j = tid;
    float acc[IPB];
#pragma unroll
    for (int i = 0; i < IPB; i++) acc[i] = 0.f;
#pragma unroll 4
    for (int k = 0; k < DIM; k++) {
        float a = attn_a[k * DIM + j];
#pragma unroll
        for (int i = 0; i < IPB; i++) acc[i] += h[i][k] * a;
    }
    float bj = attn_b[j];
#pragma unroll
    for (int i = 0; i < IPB; i++) sc[i][j] = tanhf(acc[i]) * bj;
    __syncthreads();
    if (tid < IPB) {
        float s = 0.f;
        for (int jj = 0; jj < DIM; jj++) s += sc[tid][jj];
        if (i0 + tid < N_ITEMS) g_score[i0 + tid] = s;
    }
}

// ---------------- masked softmax pooling (both contexts fused) ----------------
__global__ void k_pool(const void* __restrict__ ctx_i, const void* __restrict__ ctx_r) {
    __shared__ float sw[DIM];
    __shared__ int   sidx[DIM];
    int b = blockIdx.x, tid = threadIdx.x;
    const void* ctx = (b < B_BATCH) ? ctx_i : ctx_r;
    int bs = (b < B_BATCH) ? b : b - B_BATCH;
    int is64 = g_is64;
    float val = -1e30f; int idx = -1;
    if (tid < L_CTX) {
        int c = geti(ctx, (long long)bs * L_CTX + tid, is64);
        if (c >= 0 && g_has[c]) { idx = c; val = g_score[c]; }
    }
    sw[tid] = val; sidx[tid] = idx;
    __syncthreads();
    for (int o = 64; o > 0; o >>= 1) {
        if (tid < o) sw[tid] = fmaxf(sw[tid], sw[tid + o]);
        __syncthreads();
    }
    float m = sw[0];
    __syncthreads();
    float ex = (idx >= 0) ? expf(val - m) : 0.f;
    sw[tid] = ex;
    __syncthreads();
    for (int o = 64; o > 0; o >>= 1) {
        if (tid < o) sw[tid] += sw[tid + o];
        __syncthreads();
    }
    float s = sw[0];
    float invs = (s > 0.f) ? 1.f / s : 0.f;
    __syncthreads();
    sw[tid] = ex;
    __syncthreads();
    float acc = 0.f;
    for (int l = 0; l < L_CTX; l++) {
        float wgt = sw[l];
        if (wgt > 0.f) acc += wgt * g_item[(size_t)sidx[l] * DIM + tid];
    }
    g_pool[(size_t)b * DIM + tid] = acc * invs;
}

// ---------------- batched 2-layer projection: relu(relu(X@W1+b1)@W2+b2) ----------------
#define RPB 16
__global__ void k_proj(const float* __restrict__ W1, const float* __restrict__ b1,
                       const float* __restrict__ W2, const float* __restrict__ b2,
                       float* __restrict__ p_init, float* __restrict__ p_resp) {
    __shared__ float xs[RPB][DIM];
    int j = threadIdx.x & 127, h = threadIdx.x >> 7;   // 256 threads
    int r0 = blockIdx.x * RPB;
    for (int idx = threadIdx.x; idx < RPB * DIM / 4; idx += 256)
        ((float4*)&xs[0][0])[idx] = ((const float4*)g_pool)[(size_t)r0 * (DIM / 4) + idx];
    __syncthreads();
    int rb = h * (RPB / 2);
    float acc[RPB / 2];
    float bb = b1[j];
#pragma unroll
    for (int r = 0; r < RPB / 2; r++) acc[r] = bb;
#pragma unroll 4
    for (int k = 0; k < DIM; k++) {
        float wv = W1[k * DIM + j];
#pragma unroll
        for (int r = 0; r < RPB / 2; r++) acc[r] += xs[rb + r][k] * wv;
    }
    __syncthreads();
#pragma unroll
    for (int r = 0; r < RPB / 2; r++) xs[rb + r][j] = fmaxf(acc[r], 0.f);
    __syncthreads();
    float bb2 = b2[j];
#pragma unroll
    for (int r = 0; r < RPB / 2; r++) acc[r] = bb2;
#pragma unroll 4
    for (int k = 0; k < DIM; k++) {
        float wv = W2[k * DIM + j];
#pragma unroll
        for (int r = 0; r < RPB / 2; r++) acc[r] += xs[rb + r][k] * wv;
    }
#pragma unroll
    for (int r = 0; r < RPB / 2; r++) {
        int row = r0 + rb + r;
        float val = fmaxf(acc[r], 0.f);
        if (row < B_BATCH) p_init[(size_t)row * DIM + j] = val;
        else               p_resp[(size_t)(row - B_BATCH) * DIM + j] = val;
    }
}

// ---------------- batched 2-layer e-projection on concat(p_init,p_resp) ----------------
#define ERPB 16
__global__ void k_eproj(const float* __restrict__ W1, const float* __restrict__ b1,
                        const float* __restrict__ W2, const float* __restrict__ b2,
                        const float* __restrict__ p_init, const float* __restrict__ p_resp,
                        float* __restrict__ out) {
    __shared__ float xs[ERPB][2 * DIM];
    int j = threadIdx.x & 127, h = threadIdx.x >> 7;   // 256 threads
    int r0 = blockIdx.x * ERPB;
    for (int idx = threadIdx.x; idx < ERPB * DIM / 4; idx += 256) {
        int rr = idx / (DIM / 4), kk = idx % (DIM / 4);
        ((float4*)&xs[rr][0])[kk]       = ((const float4*)p_init)[(size_t)(r0 + rr) * (DIM / 4) + kk];
        ((float4*)&xs[rr][DIM])[kk]     = ((const float4*)p_resp)[(size_t)(r0 + rr) * (DIM / 4) + kk];
    }
    __syncthreads();
    int rb = h * (ERPB / 2);
    float acc[ERPB / 2];
    float bb = b1[j];
#pragma unroll
    for (int r = 0; r < ERPB / 2; r++) acc[r] = bb;
#pragma unroll 4
    for (int k = 0; k < 2 * DIM; k++) {
        float wv = W1[k * DIM + j];
#pragma unroll
        for (int r = 0; r < ERPB / 2; r++) acc[r] += xs[rb + r][k] * wv;
    }
    __syncthreads();
#pragma unroll
    for (int r = 0; r < ERPB / 2; r++) xs[rb + r][j] = fmaxf(acc[r], 0.f);
    __syncthreads();
    float bb2 = b2[j];
#pragma unroll
    for (int r = 0; r < ERPB / 2; r++) acc[r] = bb2;
#pragma unroll 4
    for (int k = 0; k < DIM; k++) {
        float wv = W2[k * DIM + j];
#pragma unroll
        for (int r = 0; r < ERPB / 2; r++) acc[r] += xs[rb + r][k] * wv;
    }
#pragma unroll
    for (int r = 0; r < ERPB / 2; r++)
        out[(size_t)(r0 + rb + r) * DIM + j] = fmaxf(acc[r], 0.f);
}

// ---------------- launch ----------------
extern "C" void kernel_launch(void* const* d_in, const int* in_sizes, int n_in,
                              void* d_out, int out_size) {
    const void*  ei     = d_in[0];
    const void*  et     = d_in[1];
    const void*  ctx_i  = d_in[2];
    const void*  ctx_r  = d_in[3];
    const float* basis  = (const float*)d_in[4];
    const float* comp   = (const float*)d_in[5];
    const float* root   = (const float*)d_in[6];
    const float* bias   = (const float*)d_in[7];
    const float* attn_a = (const float*)d_in[8];
    const float* attn_b = (const float*)d_in[9];
    const float* fc1_w  = (const float*)d_in[10];
    const float* fc1_b  = (const float*)d_in[11];
    const float* fc2_w  = (const float*)d_in[12];
    const float* fc2_b  = (const float*)d_in[13];
    const float* efc1_w = (const float*)d_in[14];
    const float* efc1_b = (const float*)d_in[15];
    const float* efc2_w = (const float*)d_in[16];
    const float* efc2_b = (const float*)d_in[17];
    float* out = (float*)d_out;

    float* p_init = out + B_BATCH * DIM;       // output layout: [profile | p_init | p_resp]
    float* p_resp = out + 2 * B_BATCH * DIM;

    k_detect<<<1, 32>>>((const int*)ei);
    k_zero<<<(N_USERS + 255) / 256, 256>>>();
    k_wmsg<<<N_ITEMS, DIM>>>(basis, comp);
    k_hist<<<(E_EDGES + 255) / 256, 256>>>(ei, et);
    k_scan<<<2, 1024>>>();
    k_scatter<<<(E_EDGES + 255) / 256, 256>>>();
    k_user<<<N_USERS / 8, 256>>>(root, bias);
    k_item<<<N_ITEMS / 8, 256>>>();
    k_score<<<(N_ITEMS + IPB - 1) / IPB, 128>>>(attn_a, attn_b);
    k_pool<<<2 * B_BATCH, DIM>>>(ctx_i, ctx_r);
    k_proj<<<2 * B_BATCH / RPB, 256>>>(fc1_w, fc1_b, fc2_w, fc2_b, p_init, p_resp);
    k_eproj<<<B_BATCH / ERPB, 256>>>(efc1_w, efc1_b, efc2_w, efc2_b, p_init, p_resp, out);
}

// round 3
// speedup vs baseline: 1.1961x; 1.1082x over previous
#include <cuda_runtime.h>
#include <cuda_fp16.h>
#include <math.h>

#define N_ITEMS 7000
#define N_USERS 30000
#define N_NODES 37000
#define DIM     128
#define E_EDGES 400000
#define R_REL   10
#define NBASES  8
#define B_BATCH 512
#define L_CTX   100

// ---------------- device scratch (static; no allocation) ----------------
__device__ __half g_wmsg[(size_t)R_REL * N_ITEMS * DIM];  // 17.9 MB (fp16)
__device__ __half g_userh[(size_t)N_USERS * DIM];         //  7.7 MB (fp16)
__device__ float  g_item[(size_t)N_ITEMS * DIM];          //  3.58 MB
__device__ float  g_score[N_ITEMS];
__device__ int    g_has[N_ITEMS];

__device__ int g_cnt_src[N_ITEMS];
__device__ int g_off_src[N_ITEMS + 1];
__device__ int g_csr_src[E_EDGES];        // user-local id per edge, grouped by src item

__device__ int g_cnt_dst[N_USERS];
__device__ int g_off_dst[N_USERS + 1];
__device__ int g_csr_dst[E_EDGES];        // packed src*16+type, grouped by dst user

__device__ unsigned int g_pack[E_EDGES];  // (s<<19)|(t<<15)|u

__device__ float g_pool[2 * B_BATCH * DIM];
__device__ int   g_is64;

__device__ __forceinline__ int geti(const void* p, long long i, int is64) {
    if (is64) return (int)((const long long*)p)[i];
    return ((const int*)p)[i];
}

// ---------------- zero per-call state + dtype sniff ----------------
__global__ void k_zero(const int* ei32) {
    int i = blockIdx.x * blockDim.x + threadIdx.x;
    if (i == 0) {
        int s = 0;
        for (int k = 1; k < 64; k += 2) s |= ei32[k];  // int64 -> high words all 0
        g_is64 = (s == 0) ? 1 : 0;
    }
    if (i < N_ITEMS) g_cnt_src[i] = 0;
    if (i < N_USERS) g_cnt_dst[i] = 0;
}

// ---------------- per-(relation,item) message table (fp16 out) ----------------
__global__ void k_wmsg(const float* __restrict__ basis, const float* __restrict__ comp) {
    __shared__ float sc[R_REL * NBASES];
    int i = blockIdx.x;
    int d = threadIdx.x;
    if (d < R_REL * NBASES) sc[d] = comp[d];
    __syncthreads();
    float bv[NBASES];
#pragma unroll
    for (int b = 0; b < NBASES; b++)
        bv[b] = basis[(size_t)b * N_NODES * DIM + (size_t)i * DIM + d];
#pragma unroll
    for (int r = 0; r < R_REL; r++) {
        float acc = 0.f;
#pragma unroll
        for (int b = 0; b < NBASES; b++) acc += sc[r * NBASES + b] * bv[b];
        g_wmsg[((size_t)r * N_ITEMS + i) * DIM + d] = __float2half(acc);
    }
}

// ---------------- histogram + edge packing ----------------
__global__ void k_hist(const void* __restrict__ ei, const void* __restrict__ et) {
    int e = blockIdx.x * blockDim.x + threadIdx.x;
    if (e >= E_EDGES) return;
    int is64 = g_is64;
    int s = geti(ei, e, is64);
    int u = geti(ei, (long long)E_EDGES + e, is64) - N_ITEMS;
    int t = geti(et, e, is64);
    g_pack[e] = ((unsigned)s << 19) | ((unsigned)t << 15) | (unsigned)u;
    atomicAdd(&g_cnt_src[s], 1);
    atomicAdd(&g_cnt_dst[u], 1);
}

// ---------------- warp-shuffle exclusive scan (both arrays, 2 blocks) ----------------
__device__ void scan_dev(const int* __restrict__ cnt, int* __restrict__ off, int n) {
    __shared__ int wsum[32];
    int lane = threadIdx.x & 31, w = threadIdx.x >> 5;
    int carry = 0;
    for (int base = 0; base < n; base += 1024) {
        int i = base + (int)threadIdx.x;
        int v = (i < n) ? cnt[i] : 0;
        int x = v;
#pragma unroll
        for (int o = 1; o < 32; o <<= 1) {
            int y = __shfl_up_sync(0xffffffffu, x, o);
            if (lane >= o) x += y;
        }
        if (lane == 31) wsum[w] = x;
        __syncthreads();
        if (w == 0) {
            int s = wsum[lane];
#pragma unroll
            for (int o = 1; o < 32; o <<= 1) {
                int y = __shfl_up_sync(0xffffffffu, s, o);
                if (lane >= o) s += y;
            }
            wsum[lane] = s;
        }
        __syncthreads();
        int woff = (w > 0) ? wsum[w - 1] : 0;
        if (i < n) off[i] = carry + woff + x - v;
        carry += wsum[31];
        __syncthreads();
    }
    if (threadIdx.x == 0) off[n] = carry;
}
__global__ void k_scan() {
    if (blockIdx.x == 0) scan_dev(g_cnt_src, g_off_src, N_ITEMS);
    else                 scan_dev(g_cnt_dst, g_off_dst, N_USERS);
}

// ---------------- CSR scatter (reuses cnt as countdown cursors) ----------------
__global__ void k_scatter() {
    int e = blockIdx.x * blockDim.x + threadIdx.x;
    if (e >= E_EDGES) return;
    unsigned pk = g_pack[e];
    int s = (int)(pk >> 19);
    int t = (int)((pk >> 15) & 15u);
    int u = (int)(pk & 0x7fffu);
    int p = g_off_src[s] + (atomicAdd(&g_cnt_src[s], -1) - 1);
    g_csr_src[p] = u;
    int q = g_off_dst[u] + (atomicAdd(&g_cnt_dst[u], -1) - 1);
    g_csr_dst[q] = s * 16 + t;
}

// ---------------- per-user embedding: root + bias + sum_r mean_r (fp16 gather) ----------------
__global__ void k_user(const float* __restrict__ root, const float* __restrict__ bias) {
    __shared__ int   scnt[8][16];
    __shared__ float sinv[8][16];
    int w = threadIdx.x >> 5, lane = threadIdx.x & 31;
    int u = blockIdx.x * 8 + w;
    if (u >= N_USERS) return;
    int beg = g_off_dst[u], end = g_off_dst[u + 1];
    if (lane < 16) scnt[w][lane] = 0;
    __syncwarp();
    for (int e = beg + lane; e < end; e += 32)
        atomicAdd(&scnt[w][g_csr_dst[e] & 15], 1);
    __syncwarp();
    if (lane < 16)
        sinv[w][lane] = scnt[w][lane] > 0 ? 1.f / (float)scnt[w][lane] : 0.f;
    __syncwarp();
    float4 acc = make_float4(0.f, 0.f, 0.f, 0.f);
    for (int e = beg; e < end; e += 4) {
        int   pk[4];
        float mk[4];
        uint2 v[4];
#pragma unroll
        for (int q = 0; q < 4; q++) {
            int ee = e + q;
            bool ok = ee < end;
            pk[q] = g_csr_dst[ok ? ee : beg];
            mk[q] = ok ? 1.f : 0.f;
        }
#pragma unroll
        for (int q = 0; q < 4; q++)
            v[q] = ((const uint2*)(g_wmsg + ((size_t)(pk[q] & 15) * N_ITEMS + (pk[q] >> 4)) * DIM))[lane];
#pragma unroll
        for (int q = 0; q < 4; q++) {
            float iv = mk[q] * sinv[w][pk[q] & 15];
            float2 f0 = __half22float2(*(const __half2*)&v[q].x);
            float2 f1 = __half22float2(*(const __half2*)&v[q].y);
            acc.x += iv * f0.x; acc.y += iv * f0.y;
            acc.z += iv * f1.x; acc.w += iv * f1.y;
        }
    }
    int g = N_ITEMS + u;
    float4 rv = ((const float4*)&root[(size_t)g * DIM])[lane];
    float4 bv = ((const float4*)bias)[lane];
    uint2 o;
    *(__half2*)&o.x = __floats2half2_rn(acc.x + rv.x + bv.x, acc.y + rv.y + bv.y);
    *(__half2*)&o.y = __floats2half2_rn(acc.z + rv.z + bv.z, acc.w + rv.w + bv.w);
    ((uint2*)(g_userh + (size_t)u * DIM))[lane] = o;
}

// ---------------- per-item mean of connected users (fp16 gather) ----------------
__global__ void k_item() {
    int w = threadIdx.x >> 5, lane = threadIdx.x & 31;
    int i = blockIdx.x * 8 + w;
    if (i >= N_ITEMS) return;
    int beg = g_off_src[i], end = g_off_src[i + 1];
    float4 acc = make_float4(0.f, 0.f, 0.f, 0.f);
    for (int e = beg; e < end; e += 4) {
        float mk[4];
        uint2 v[4];
        int   uu[4];
#pragma unroll
        for (int q = 0; q < 4; q++) {
            int ee = e + q;
            bool ok = ee < end;
            uu[q] = g_csr_src[ok ? ee : beg];
            mk[q] = ok ? 1.f : 0.f;
        }
#pragma unroll
        for (int q = 0; q < 4; q++)
            v[q] = ((const uint2*)(g_userh + (size_t)uu[q] * DIM))[lane];
#pragma unroll
        for (int q = 0; q < 4; q++) {
            float2 f0 = __half22float2(*(const __half2*)&v[q].x);
            float2 f1 = __half22float2(*(const __half2*)&v[q].y);
            acc.x += mk[q] * f0.x; acc.y += mk[q] * f0.y;
            acc.z += mk[q] * f1.x; acc.w += mk[q] * f1.y;
        }
    }
    int deg = end - beg;
    float iv = deg > 0 ? 1.f / (float)deg : 0.f;
    ((float4*)&g_item[((size_t)i * DIM)])[lane] =
        make_float4(acc.x * iv, acc.y * iv, acc.z * iv, acc.w * iv);
    if (lane == 0) g_has[i] = (deg > 0) ? 1 : 0;
}

// ---------------- batched per-item attention score: tanh(h@A)·b ----------------
#define IPB 32
__global__ void k_score(const float* __restrict__ attn_a, const float* __restrict__ attn_b) {
    __shared__ float h[IPB][DIM];
    __shared__ float sc[IPB][DIM + 1];
    int i0 = blockIdx.x * IPB;
    int tid = threadIdx.x;      // 128
    for (int idx = tid; idx < IPB * DIM / 4; idx += 128) {
        int ii = idx / (DIM / 4), kk = idx % (DIM / 4);
        float4 v = (i0 + ii < N_ITEMS)
                   ? ((const float4*)&g_item[(size_t)(i0 + ii) * DIM])[kk]
                   : make_float4(0.f, 0.f, 0.f, 0.f);
        ((float4*)h[ii])[kk] = v;
    }
    __syncthreads();
    int j = tid;
    float acc[IPB];
#pragma unroll
    for (int i = 0; i < IPB; i++) acc[i] = 0.f;
#pragma unroll 4
    for (int k = 0; k < DIM; k++) {
        float a = attn_a[k * DIM + j];
#pragma unroll
        for (int i = 0; i < IPB; i++) acc[i] += h[i][k] * a;
    }
    float bj = attn_b[j];
#pragma unroll
    for (int i = 0; i < IPB; i++) sc[i][j] = tanhf(acc[i]) * bj;
    __syncthreads();
    if (tid < IPB) {
        float s = 0.f;
        for (int jj = 0; jj < DIM; jj++) s += sc[tid][jj];
        if (i0 + tid < N_ITEMS) g_score[i0 + tid] = s;
    }
}

// ---------------- masked softmax pooling (both contexts fused) ----------------
__global__ void k_pool(const void* __restrict__ ctx_i, const void* __restrict__ ctx_r) {
    __shared__ float sw[DIM];
    __shared__ int   sidx[DIM];
    int b = blockIdx.x, tid = threadIdx.x;
    const void* ctx = (b < B_BATCH) ? ctx_i : ctx_r;
    int bs = (b < B_BATCH) ? b : b - B_BATCH;
    int is64 = g_is64;
    float val = -1e30f; int idx = -1;
    if (tid < L_CTX) {
        int c = geti(ctx, (long long)bs * L_CTX + tid, is64);
        if (c >= 0 && g_has[c]) { idx = c; val = g_score[c]; }
    }
    sw[tid] = val; sidx[tid] = idx;
    __syncthreads();
    for (int o = 64; o > 0; o >>= 1) {
        if (tid < o) sw[tid] = fmaxf(sw[tid], sw[tid + o]);
        __syncthreads();
    }
    float m = sw[0];
    __syncthreads();
    float ex = (idx >= 0) ? expf(val - m) : 0.f;
    sw[tid] = ex;
    __syncthreads();
    for (int o = 64; o > 0; o >>= 1) {
        if (tid < o) sw[tid] += sw[tid + o];
        __syncthreads();
    }
    float s = sw[0];
    float invs = (s > 0.f) ? 1.f / s : 0.f;
    __syncthreads();
    sw[tid] = ex;
    __syncthreads();
    float acc = 0.f;
    for (int l = 0; l < L_CTX; l++) {
        float wgt = sw[l];
        if (wgt > 0.f) acc += wgt * g_item[(size_t)sidx[l] * DIM + tid];
    }
    g_pool[(size_t)b * DIM + tid] = acc * invs;
}

// ---------------- batched 2-layer projection: relu(relu(X@W1+b1)@W2+b2) ----------------
#define RPB 16
__global__ void k_proj(const float* __restrict__ W1, const float* __restrict__ b1,
                       const float* __restrict__ W2, const float* __restrict__ b2,
                       float* __restrict__ p_init, float* __restrict__ p_resp) {
    __shared__ float xs[RPB][DIM];
    int j = threadIdx.x & 127, h = threadIdx.x >> 7;   // 256 threads
    int r0 = blockIdx.x * RPB;
    for (int idx = threadIdx.x; idx < RPB * DIM / 4; idx += 256)
        ((float4*)&xs[0][0])[idx] = ((const float4*)g_pool)[(size_t)r0 * (DIM / 4) + idx];
    __syncthreads();
    int rb = h * (RPB / 2);
    float acc[RPB / 2];
    float bb = b1[j];
#pragma unroll
    for (int r = 0; r < RPB / 2; r++) acc[r] = bb;
#pragma unroll 4
    for (int k = 0; k < DIM; k++) {
        float wv = W1[k * DIM + j];
#pragma unroll
        for (int r = 0; r < RPB / 2; r++) acc[r] += xs[rb + r][k] * wv;
    }
    __syncthreads();
#pragma unroll
    for (int r = 0; r < RPB / 2; r++) xs[rb + r][j] = fmaxf(acc[r], 0.f);
    __syncthreads();
    float bb2 = b2[j];
#pragma unroll
    for (int r = 0; r < RPB / 2; r++) acc[r] = bb2;
#pragma unroll 4
    for (int k = 0; k < DIM; k++) {
        float wv = W2[k * DIM + j];
#pragma unroll
        for (int r = 0; r < RPB / 2; r++) acc[r] += xs[rb + r][k] * wv;
    }
#pragma unroll
    for (int r = 0; r < RPB / 2; r++) {
        int row = r0 + rb + r;
        float val = fmaxf(acc[r], 0.f);
        if (row < B_BATCH) p_init[(size_t)row * DIM + j] = val;
        else               p_resp[(size_t)(row - B_BATCH) * DIM + j] = val;
    }
}

// ---------------- batched 2-layer e-projection on concat(p_init,p_resp) ----------------
#define ERPB 16
__global__ void k_eproj(const float* __restrict__ W1, const float* __restrict__ b1,
                        const float* __restrict__ W2, const float* __restrict__ b2,
                        const float* __restrict__ p_init, const float* __restrict__ p_resp,
                        float* __restrict__ out) {
    __shared__ float xs[ERPB][2 * DIM];
    int j = threadIdx.x & 127, h = threadIdx.x >> 7;   // 256 threads
    int r0 = blockIdx.x * ERPB;
    for (int idx = threadIdx.x; idx < ERPB * DIM / 4; idx += 256) {
        int rr = idx / (DIM / 4), kk = idx % (DIM / 4);
        ((float4*)&xs[rr][0])[kk]   = ((const float4*)p_init)[(size_t)(r0 + rr) * (DIM / 4) + kk];
        ((float4*)&xs[rr][DIM])[kk] = ((const float4*)p_resp)[(size_t)(r0 + rr) * (DIM / 4) + kk];
    }
    __syncthreads();
    int rb = h * (ERPB / 2);
    float acc[ERPB / 2];
    float bb = b1[j];
#pragma unroll
    for (int r = 0; r < ERPB / 2; r++) acc[r] = bb;
#pragma unroll 4
    for (int k = 0; k < 2 * DIM; k++) {
        float wv = W1[k * DIM + j];
#pragma unroll
        for (int r = 0; r < ERPB / 2; r++) acc[r] += xs[rb + r][k] * wv;
    }
    __syncthreads();
#pragma unroll
    for (int r = 0; r < ERPB / 2; r++) xs[rb + r][j] = fmaxf(acc[r], 0.f);
    __syncthreads();
    float bb2 = b2[j];
#pragma unroll
    for (int r = 0; r < ERPB / 2; r++) acc[r] = bb2;
#pragma unroll 4
    for (int k = 0; k < DIM; k++) {
        float wv = W2[k * DIM + j];
#pragma unroll
        for (int r = 0; r < ERPB / 2; r++) acc[r] += xs[rb + r][k] * wv;
    }
#pragma unroll
    for (int r = 0; r < ERPB / 2; r++)
        out[(size_t)(r0 + rb + r) * DIM + j] = fmaxf(acc[r], 0.f);
}

// ---------------- launch ----------------
extern "C" void kernel_launch(void* const* d_in, const int* in_sizes, int n_in,
                              void* d_out, int out_size) {
    const void*  ei     = d_in[0];
    const void*  et     = d_in[1];
    const void*  ctx_i  = d_in[2];
    const void*  ctx_r  = d_in[3];
    const float* basis  = (const float*)d_in[4];
    const float* comp   = (const float*)d_in[5];
    const float* root   = (const float*)d_in[6];
    const float* bias   = (const float*)d_in[7];
    const float* attn_a = (const float*)d_in[8];
    const float* attn_b = (const float*)d_in[9];
    const float* fc1_w  = (const float*)d_in[10];
    const float* fc1_b  = (const float*)d_in[11];
    const float* fc2_w  = (const float*)d_in[12];
    const float* fc2_b  = (const float*)d_in[13];
    const float* efc1_w = (const float*)d_in[14];
    const float* efc1_b = (const float*)d_in[15];
    const float* efc2_w = (const float*)d_in[16];
    const float* efc2_b = (const float*)d_in[17];
    float* out = (float*)d_out;

    float* p_init = out + B_BATCH * DIM;       // output layout: [profile | p_init | p_resp]
    float* p_resp = out + 2 * B_BATCH * DIM;

    k_zero<<<(N_USERS + 255) / 256, 256>>>((const int*)ei);
    k_wmsg<<<N_ITEMS, DIM>>>(basis, comp);
    k_hist<<<(E_EDGES + 255) / 256, 256>>>(ei, et);
    k_scan<<<2, 1024>>>();
    k_scatter<<<(E_EDGES + 255) / 256, 256>>>();
    k_user<<<N_USERS / 8, 256>>>(root, bias);
    k_item<<<N_ITEMS / 8, 256>>>();
    k_score<<<(N_ITEMS + IPB - 1) / IPB, 128>>>(attn_a, attn_b);
    k_pool<<<2 * B_BATCH, DIM>>>(ctx_i, ctx_r);
    k_proj<<<2 * B_BATCH / RPB, 256>>>(fc1_w, fc1_b, fc2_w, fc2_b, p_init, p_resp);
    k_eproj<<<B_BATCH / ERPB, 256>>>(efc1_w, efc1_b, efc2_w, efc2_b, p_init, p_resp, out);
}